// round 10
// baseline (speedup 1.0000x reference)
#include <cuda_runtime.h>
#include <cuda_fp16.h>
#include <math.h>
#include <cstdint>

constexpr int HD = 1024;
constexpr int NH = 8;
constexpr int DH = 128;
constexpr int BB = 4;
constexpr int TT = 2048;
constexpr int MM = BB * TT; // 8192

typedef unsigned long long ull;

// ---- scratch (allocation-free) ----
__device__ __half g_xn[MM * 1024];          // LN out fp16
__device__ __half g_w[4][1024 * 1024];      // weights fp16 (contiguous: q,k,v,o)
__device__ __half g_q[32 * TT * 128];       // [B*NH][T][128], pre-scaled
__device__ __half g_k[32 * TT * 128];
__device__ __half g_v[32 * TT * 128];
__device__ __half g_attn[MM * 1024];        // attn fp16 [B,T,1024]

// ============================================================
// helpers
// ============================================================
__device__ __forceinline__ uint32_t s2u(const void* p) {
    uint32_t a;
    asm("{ .reg .u64 t; cvta.to.shared.u64 t, %1; cvt.u32.u64 %0, t; }" : "=r"(a) : "l"(p));
    return a;
}
__device__ __forceinline__ void cpasync16(uint32_t smem, const void* g) {
    asm volatile("cp.async.cg.shared.global [%0], [%1], 16;" :: "r"(smem), "l"(g));
}
__device__ __forceinline__ void cpcommit() { asm volatile("cp.async.commit_group;" ::: "memory"); }
template<int N> __device__ __forceinline__ void cpwait() {
    asm volatile("cp.async.wait_group %0;" :: "n"(N) : "memory");
}
__device__ __forceinline__ void ldsm4(uint32_t* r, uint32_t addr) {
    asm volatile("ldmatrix.sync.aligned.m8n8.x4.shared.b16 {%0,%1,%2,%3}, [%4];"
                 : "=r"(r[0]), "=r"(r[1]), "=r"(r[2]), "=r"(r[3]) : "r"(addr));
}
__device__ __forceinline__ void ldsm4t(uint32_t* r, uint32_t addr) {
    asm volatile("ldmatrix.sync.aligned.m8n8.x4.trans.shared.b16 {%0,%1,%2,%3}, [%4];"
                 : "=r"(r[0]), "=r"(r[1]), "=r"(r[2]), "=r"(r[3]) : "r"(addr));
}
__device__ __forceinline__ void mma16816(float* d, const uint32_t* a, uint32_t b0, uint32_t b1) {
    asm volatile("mma.sync.aligned.m16n8k16.row.col.f32.f16.f16.f32 "
                 "{%0,%1,%2,%3}, {%4,%5,%6,%7}, {%8,%9}, {%0,%1,%2,%3};"
                 : "+f"(d[0]), "+f"(d[1]), "+f"(d[2]), "+f"(d[3])
                 : "r"(a[0]), "r"(a[1]), "r"(a[2]), "r"(a[3]), "r"(b0), "r"(b1));
}
__device__ __forceinline__ uint32_t pack_h2(float a, float b) {
    __half2 h = __floats2half2_rn(a, b);
    return *(uint32_t*)&h;
}

// ============================================================
// LayerNorm -> fp16 [row][1024]
// ============================================================
__global__ void __launch_bounds__(256) ln_kernel(
    const float* __restrict__ x, const float* __restrict__ gamma,
    const float* __restrict__ beta, __half* __restrict__ xn)
{
    int row = blockIdx.x;
    int tid = threadIdx.x;
    const float* xr = x + (size_t)row * HD;
    float4 v = *(const float4*)&xr[tid * 4];
    float s  = v.x + v.y + v.z + v.w;
    float ss = v.x * v.x + v.y * v.y + v.z * v.z + v.w * v.w;
    #pragma unroll
    for (int o = 16; o; o >>= 1) {
        s  += __shfl_xor_sync(0xffffffffu, s,  o);
        ss += __shfl_xor_sync(0xffffffffu, ss, o);
    }
    __shared__ float rs[8], rss[8];
    if ((tid & 31) == 0) { rs[tid >> 5] = s; rss[tid >> 5] = ss; }
    __syncthreads();
    s = 0.f; ss = 0.f;
    #pragma unroll
    for (int i = 0; i < 8; i++) { s += rs[i]; ss += rss[i]; }
    float mu  = s * (1.0f / HD);
    float inv = rsqrtf(ss * (1.0f / HD) - mu * mu + 1e-5f);
    float4 g  = *(const float4*)&gamma[tid * 4];
    float4 be = *(const float4*)&beta[tid * 4];
    uint32_t p0 = pack_h2((v.x - mu) * inv * g.x + be.x, (v.y - mu) * inv * g.y + be.y);
    uint32_t p1 = pack_h2((v.z - mu) * inv * g.z + be.z, (v.w - mu) * inv * g.w + be.w);
    ull pk = (ull)p0 | ((ull)p1 << 32);
    *(ull*)&xn[(size_t)row * 1024 + tid * 4] = pk;
}

// all four weights -> fp16 in one launch
__global__ void __launch_bounds__(256) conv_half4(
    const float* __restrict__ W0, const float* __restrict__ W1,
    const float* __restrict__ W2, const float* __restrict__ W3,
    __half* __restrict__ Wh)
{
    int sel = blockIdx.x >> 10;
    const float* src = (sel == 0) ? W0 : (sel == 1) ? W1 : (sel == 2) ? W2 : W3;
    int i = (blockIdx.x & 1023) * 256 + threadIdx.x;
    float4 v = ((const float4*)src)[i];
    ull pk = (ull)pack_h2(v.x, v.y) | ((ull)pack_h2(v.z, v.w) << 32);
    *(ull*)&Wh[((size_t)sel << 20) + (size_t)i * 4] = pk;
}

// ============================================================
// mma.sync fp16 GEMM core (unchanged): CTA 128x128, 8 warps,
// warp 32x64, K-chunk 32, 3-stage cp.async.
// ============================================================
constexpr int GPITCH = 80;
constexpr int MAT_STAGE = 128 * GPITCH;
constexpr int STAGE_BYTES = 2 * MAT_STAGE;
constexpr int GSTG = 3;
constexpr int GEMM_SMEM = GSTG * STAGE_BYTES;
constexpr int NCHUNK = 32;

__device__ __forceinline__ void gemm_load_chunk(
    const __half* __restrict__ A2, const __half* __restrict__ B2,
    int m0, int n0, int c, uint32_t sbase, int tid)
{
    int s = c % GSTG;
    int kc = c * 32;
    uint32_t aSt = sbase + s * STAGE_BYTES;
    uint32_t bSt = aSt + MAT_STAGE;
    #pragma unroll
    for (int p = 0; p < 2; p++) {
        int e = tid + (p << 8);
        int r = e >> 2, cc = e & 3;
        cpasync16(aSt + r * GPITCH + cc * 16, A2 + (size_t)(m0 + r) * 1024 + kc + cc * 8);
        cpasync16(bSt + r * GPITCH + cc * 16, B2 + (size_t)(n0 + r) * 1024 + kc + cc * 8);
    }
    cpcommit();
}

__device__ __forceinline__ void gemm_core(
    const __half* A2, const __half* B2,
    int m0, int n0, uint32_t sbase, int tid, int lane, int wm, int wn,
    float d[2][8][4])
{
    gemm_load_chunk(A2, B2, m0, n0, 0, sbase, tid);
    gemm_load_chunk(A2, B2, m0, n0, 1, sbase, tid);
    int lr = lane & 15;
    int lk = (lane >> 4) << 3;
    for (int c = 0; c < NCHUNK; c++) {
        cpwait<1>();
        __syncthreads();
        if (c + 2 < NCHUNK) gemm_load_chunk(A2, B2, m0, n0, c + 2, sbase, tid);
        else cpcommit();
        uint32_t aSt = sbase + (c % GSTG) * STAGE_BYTES;
        uint32_t bSt = aSt + MAT_STAGE;
        #pragma unroll
        for (int k16 = 0; k16 < 2; k16++) {
            uint32_t a[2][4], b[4][4];
            #pragma unroll
            for (int mt = 0; mt < 2; mt++)
                ldsm4(a[mt], aSt + (wm * 32 + mt * 16 + lr) * GPITCH + (k16 * 16 + lk) * 2);
            #pragma unroll
            for (int nt = 0; nt < 4; nt++)
                ldsm4(b[nt], bSt + (wn * 64 + nt * 16 + lr) * GPITCH + (k16 * 16 + lk) * 2);
            #pragma unroll
            for (int mt = 0; mt < 2; mt++)
                #pragma unroll
                for (int n8 = 0; n8 < 8; n8++) {
                    int nt = n8 >> 1, odd = n8 & 1;
                    mma16816(d[mt][n8], a[mt], b[nt][odd], b[nt][odd + 2]);
                }
        }
        __syncthreads();
    }
}

// Fused QKV: B = concat(Wq,Wk,Wv) 3072x1024; fp16 out [B,NH,T,128]
__global__ void __launch_bounds__(256, 2) gemm_mma_qkv(
    const __half* __restrict__ A2, const __half* __restrict__ Ball,
    __half* __restrict__ Qo, __half* __restrict__ Ko, __half* __restrict__ Vo,
    float qscale)
{
    extern __shared__ char sm[];
    uint32_t sbase = s2u(sm);
    int tid = threadIdx.x, lane = tid & 31, warp = tid >> 5;
    int wm = warp >> 1, wn = warp & 1;
    int m0 = blockIdx.y << 7, n0 = blockIdx.x << 7;
    int sel = n0 >> 10;
    __half* outp = (sel == 0) ? Qo : (sel == 1) ? Ko : Vo;
    float scale = (sel == 0) ? qscale : 1.0f;

    float d[2][8][4];
    #pragma unroll
    for (int i = 0; i < 2; i++)
        #pragma unroll
        for (int j = 0; j < 8; j++)
            #pragma unroll
            for (int q = 0; q < 4; q++) d[i][j][q] = 0.f;

    gemm_core(A2, Ball, m0, n0, sbase, tid, lane, wm, wn, d);

    int mb = m0 + wm * 32 + (lane >> 2);
    int nb = n0 + wn * 64 + (lane & 3) * 2;
    #pragma unroll
    for (int mt = 0; mt < 2; mt++) {
        #pragma unroll
        for (int n8 = 0; n8 < 8; n8++) {
            int n = nb + n8 * 8;
            #pragma unroll
            for (int half = 0; half < 2; half++) {
                int m = mb + mt * 16 + half * 8;
                float c0 = d[mt][n8][half * 2] * scale, c1 = d[mt][n8][half * 2 + 1] * scale;
                int bI = m >> 11, t = m & 2047;
                int h = (n >> 7) & 7, dd = n & 127;
                size_t base = ((size_t)(bI * NH + h) * TT + t) * 128 + dd;
                *(uint32_t*)&outp[base] = pack_h2(c0, c1);
            }
        }
    }
}

// Output-projection: fp32 + residual
__global__ void __launch_bounds__(256, 2) gemm_mma_out(
    const __half* __restrict__ A2, const __half* __restrict__ B2,
    float* __restrict__ C, const float* __restrict__ R)
{
    extern __shared__ char sm[];
    uint32_t sbase = s2u(sm);
    int tid = threadIdx.x, lane = tid & 31, warp = tid >> 5;
    int wm = warp >> 1, wn = warp & 1;
    int m0 = blockIdx.y << 7, n0 = blockIdx.x << 7;

    float d[2][8][4];
    #pragma unroll
    for (int i = 0; i < 2; i++)
        #pragma unroll
        for (int j = 0; j < 8; j++)
            #pragma unroll
            for (int q = 0; q < 4; q++) d[i][j][q] = 0.f;

    gemm_core(A2, B2, m0, n0, sbase, tid, lane, wm, wn, d);

    int mb = m0 + wm * 32 + (lane >> 2);
    int nb = n0 + wn * 64 + (lane & 3) * 2;
    #pragma unroll
    for (int mt = 0; mt < 2; mt++) {
        #pragma unroll
        for (int n8 = 0; n8 < 8; n8++) {
            int n = nb + n8 * 8;
            #pragma unroll
            for (int half = 0; half < 2; half++) {
                int m = mb + mt * 16 + half * 8;
                size_t idx = (size_t)m * HD + n;
                float2 rr = *(const float2*)&R[idx];
                *(float2*)&C[idx] = make_float2(d[mt][n8][half * 2] + rr.x,
                                                d[mt][n8][half * 2 + 1] + rr.y);
            }
        }
    }
}

// ============================================================
// Flash attention FA2: BM=128, BN=128, 8 warps x 16 rows.
// K-block = 128 -> qb+1 steps; softmax overhead amortized 2x.
// Q re-read via ldmatrix (keeps regs < spill point).
// S-accum fragments reused directly as A of P@V.
// Q pre-scaled by scale*log2(e); base-2 softmax.
// ============================================================
constexpr int FPB = 272;                       // row pitch bytes
constexpr int FL_Q = 0;                        // 128 x FPB
constexpr int FL_K = FL_Q + 128 * FPB;         // 2 bufs x 128 x FPB
constexpr int FL_V = FL_K + 2 * 128 * FPB;
constexpr int FLASH_SMEM = FL_V + 2 * 128 * FPB;   // 174080 B

__global__ void __launch_bounds__(256) flash_mma(
    const __half* __restrict__ Q2, const __half* __restrict__ K2,
    const __half* __restrict__ V2, __half* __restrict__ Aout)
{
    extern __shared__ char sm[];
    uint32_t sb = s2u(sm);
    int tid = threadIdx.x, lane = tid & 31, w = tid >> 5;
    int g = lane >> 2, tig = lane & 3;
    int qb = gridDim.x - 1 - blockIdx.x;      // largest tiles first
    int bh = blockIdx.y;
    int q0 = qb << 7;
    const __half* qp = Q2 + (size_t)bh * TT * 128;
    const __half* kp = K2 + (size_t)bh * TT * 128;
    const __half* vp = V2 + (size_t)bh * TT * 128;

    // prologue: Q tile + K/V block 0 (128 rows each) in one group
    #pragma unroll
    for (int p = 0; p < 8; p++) {
        int e = tid + (p << 8);
        int r = e >> 4, c = e & 15;
        cpasync16(sb + FL_Q + r * FPB + c * 16, qp + (size_t)(q0 + r) * 128 + c * 8);
        cpasync16(sb + FL_K + r * FPB + c * 16, kp + (size_t)r * 128 + c * 8);
        cpasync16(sb + FL_V + r * FPB + c * 16, vp + (size_t)r * 128 + c * 8);
    }
    cpcommit();

    int lr = lane & 15;
    int lk = (lane >> 4) << 3;

    float o[16][4];
    #pragma unroll
    for (int i = 0; i < 16; i++)
        #pragma unroll
        for (int j = 0; j < 4; j++) o[i][j] = 0.f;
    float m0r = -1e30f, m1r = -1e30f, l0r = 0.f, l1r = 0.f;

    int nkb = qb + 1;
    for (int kb = 0; kb < nkb; kb++) {
        int buf = kb & 1;
        __syncthreads();   // all warps done reading buf^1 (step kb-2)
        if (kb + 1 < nkb) {
            int kn0 = (kb + 1) << 7;
            uint32_t kD = sb + FL_K + (buf ^ 1) * 128 * FPB;
            uint32_t vD = sb + FL_V + (buf ^ 1) * 128 * FPB;
            #pragma unroll
            for (int p = 0; p < 8; p++) {
                int e = tid + (p << 8);
                int r = e >> 4, c = e & 15;
                cpasync16(kD + r * FPB + c * 16, kp + (size_t)(kn0 + r) * 128 + c * 8);
                cpasync16(vD + r * FPB + c * 16, vp + (size_t)(kn0 + r) * 128 + c * 8);
            }
        }
        cpcommit();
        cpwait<1>();
        __syncthreads();

        uint32_t kB = sb + FL_K + buf * 128 * FPB;
        uint32_t vB = sb + FL_V + buf * 128 * FPB;

        // ---- S = Q K^T : warp computes 16x128 ----
        float s[16][4];
        #pragma unroll
        for (int i = 0; i < 16; i++)
            #pragma unroll
            for (int j = 0; j < 4; j++) s[i][j] = 0.f;
        #pragma unroll
        for (int k16 = 0; k16 < 8; k16++) {
            uint32_t a[4];
            ldsm4(a, sb + FL_Q + (w * 16 + lr) * FPB + (k16 * 16 + lk) * 2);
            #pragma unroll
            for (int t = 0; t < 8; t++) {
                uint32_t b[4];
                ldsm4(b, kB + (t * 16 + lr) * FPB + (k16 * 16 + lk) * 2);
                mma16816(s[2 * t],     a, b[0], b[2]);
                mma16816(s[2 * t + 1], a, b[1], b[3]);
            }
        }

        // causal mask: only the diagonal block
        if (kb == qb) {
            int rg0 = q0 + w * 16 + g;
            int rg1 = rg0 + 8;
            int cgb = (kb << 7) + tig * 2;
            #pragma unroll
            for (int j = 0; j < 16; j++) {
                int cg = cgb + j * 8;
                if (cg     > rg0) s[j][0] = -1e30f;
                if (cg + 1 > rg0) s[j][1] = -1e30f;
                if (cg     > rg1) s[j][2] = -1e30f;
                if (cg + 1 > rg1) s[j][3] = -1e30f;
            }
        }

        // ---- warp-local softmax (rows g, g+8) ----
        float mx0 = -1e30f, mx1 = -1e30f;
        #pragma unroll
        for (int j = 0; j < 16; j++) {
            mx0 = fmaxf(mx0, fmaxf(s[j][0], s[j][1]));
            mx1 = fmaxf(mx1, fmaxf(s[j][2], s[j][3]));
        }
        mx0 = fmaxf(mx0, __shfl_xor_sync(0xffffffffu, mx0, 1));
        mx0 = fmaxf(mx0, __shfl_xor_sync(0xffffffffu, mx0, 2));
        mx1 = fmaxf(mx1, __shfl_xor_sync(0xffffffffu, mx1, 1));
        mx1 = fmaxf(mx1, __shfl_xor_sync(0xffffffffu, mx1, 2));
        float mn0 = fmaxf(m0r, mx0), mn1 = fmaxf(m1r, mx1);
        float al0 = exp2f(m0r - mn0), al1 = exp2f(m1r - mn1);
        m0r = mn0; m1r = mn1;

        float ps0 = 0.f, ps1 = 0.f;
        #pragma unroll
        for (int j = 0; j < 16; j++) {
            s[j][0] = exp2f(s[j][0] - mn0);
            s[j][1] = exp2f(s[j][1] - mn0);
            s[j][2] = exp2f(s[j][2] - mn1);
            s[j][3] = exp2f(s[j][3] - mn1);
            ps0 += s[j][0] + s[j][1];
            ps1 += s[j][2] + s[j][3];
        }
        ps0 += __shfl_xor_sync(0xffffffffu, ps0, 1);
        ps0 += __shfl_xor_sync(0xffffffffu, ps0, 2);
        ps1 += __shfl_xor_sync(0xffffffffu, ps1, 1);
        ps1 += __shfl_xor_sync(0xffffffffu, ps1, 2);
        l0r = l0r * al0 + ps0;
        l1r = l1r * al1 + ps1;

        // rescale O (skip when max unchanged warp-wide)
        if (!__all_sync(0xffffffffu, (al0 == 1.f) & (al1 == 1.f))) {
            #pragma unroll
            for (int j = 0; j < 16; j++) {
                o[j][0] *= al0; o[j][1] *= al0;
                o[j][2] *= al1; o[j][3] *= al1;
            }
        }

        // P fragments straight from S accumulators
        uint32_t pa[8][4];
        #pragma unroll
        for (int c = 0; c < 8; c++) {
            pa[c][0] = pack_h2(s[2 * c][0],     s[2 * c][1]);
            pa[c][1] = pack_h2(s[2 * c][2],     s[2 * c][3]);
            pa[c][2] = pack_h2(s[2 * c + 1][0], s[2 * c + 1][1]);
            pa[c][3] = pack_h2(s[2 * c + 1][2], s[2 * c + 1][3]);
        }

        // ---- O += P V : warp computes 16x128 ----
        #pragma unroll
        for (int c = 0; c < 8; c++) {
            #pragma unroll
            for (int j = 0; j < 8; j++) {
                uint32_t bt[4];
                ldsm4t(bt, vB + (c * 16 + lr) * FPB + (j * 16 + lk) * 2);
                mma16816(o[2 * j],     pa[c], bt[0], bt[1]);
                mma16816(o[2 * j + 1], pa[c], bt[2], bt[3]);
            }
        }
    }

    // epilogue: normalize, fp16 store [B,T,1024]
    float inv0 = 1.f / l0r, inv1 = 1.f / l1r;
    int b = bh >> 3, h = bh & 7;
    int t0 = q0 + w * 16 + g;
    #pragma unroll
    for (int j = 0; j < 16; j++) {
        int d = j * 8 + tig * 2;
        size_t base0 = (size_t)(b * TT + t0) * 1024 + h * 128 + d;
        size_t base1 = base0 + 8 * 1024;
        *(uint32_t*)&Aout[base0] = pack_h2(o[j][0] * inv0, o[j][1] * inv0);
        *(uint32_t*)&Aout[base1] = pack_h2(o[j][2] * inv1, o[j][3] * inv1);
    }
}

// ============================================================
// Launch
// ============================================================
extern "C" void kernel_launch(void* const* d_in, const int* in_sizes, int n_in,
                              void* d_out, int out_size)
{
    const float* x     = (const float*)d_in[0];
    const float* gamma = (const float*)d_in[1];
    const float* beta  = (const float*)d_in[2];
    const float* Wq    = (const float*)d_in[3];
    const float* Wk    = (const float*)d_in[4];
    const float* Wv    = (const float*)d_in[5];
    const float* Wo    = (const float*)d_in[6];
    float* out = (float*)d_out;

    __half *xn, *w, *q, *k, *v, *attn;
    cudaGetSymbolAddress((void**)&xn,   g_xn);
    cudaGetSymbolAddress((void**)&w,    g_w);
    cudaGetSymbolAddress((void**)&q,    g_q);
    cudaGetSymbolAddress((void**)&k,    g_k);
    cudaGetSymbolAddress((void**)&v,    g_v);
    cudaGetSymbolAddress((void**)&attn, g_attn);

    cudaFuncSetAttribute(gemm_mma_qkv, cudaFuncAttributeMaxDynamicSharedMemorySize, GEMM_SMEM);
    cudaFuncSetAttribute(gemm_mma_out, cudaFuncAttributeMaxDynamicSharedMemorySize, GEMM_SMEM);
    cudaFuncSetAttribute(flash_mma, cudaFuncAttributeMaxDynamicSharedMemorySize, FLASH_SMEM);

    ln_kernel<<<MM, 256>>>(x, gamma, beta, xn);
    conv_half4<<<4096, 256>>>(Wq, Wk, Wv, Wo, w);

    // scale*log2(e) folded into Q so softmax runs in base 2
    const float qscale = 0.08838834764831845f * 1.44269504088896341f;
    gemm_mma_qkv<<<dim3(24, 64), 256, GEMM_SMEM>>>(xn, w, q, k, v, qscale);

    flash_mma<<<dim3(TT / 128, BB * NH), 256, FLASH_SMEM>>>(q, k, v, attn);

    gemm_mma_out<<<dim3(8, 64), 256, GEMM_SMEM>>>(attn, w + ((size_t)3 << 20), out, x);
}

// round 11
// speedup vs baseline: 1.0173x; 1.0173x over previous
#include <cuda_runtime.h>
#include <cuda_fp16.h>
#include <math.h>
#include <cstdint>

constexpr int HD = 1024;
constexpr int NH = 8;
constexpr int DH = 128;
constexpr int BB = 4;
constexpr int TT = 2048;
constexpr int MM = BB * TT; // 8192

typedef unsigned long long ull;

// ---- scratch (allocation-free) ----
__device__ __half g_xn[MM * 1024];          // LN out fp16
__device__ __half g_w[4][1024 * 1024];      // weights fp16 (contiguous: q,k,v,o)
__device__ __half g_q[32 * TT * 128];       // [B*NH][T][128], pre-scaled
__device__ __half g_k[32 * TT * 128];
__device__ __half g_v[32 * TT * 128];
__device__ __half g_attn[MM * 1024];        // attn fp16 [B,T,1024]

// ============================================================
// helpers
// ============================================================
__device__ __forceinline__ uint32_t s2u(const void* p) {
    uint32_t a;
    asm("{ .reg .u64 t; cvta.to.shared.u64 t, %1; cvt.u32.u64 %0, t; }" : "=r"(a) : "l"(p));
    return a;
}
__device__ __forceinline__ void cpasync16(uint32_t smem, const void* g) {
    asm volatile("cp.async.cg.shared.global [%0], [%1], 16;" :: "r"(smem), "l"(g));
}
__device__ __forceinline__ void cpcommit() { asm volatile("cp.async.commit_group;" ::: "memory"); }
template<int N> __device__ __forceinline__ void cpwait() {
    asm volatile("cp.async.wait_group %0;" :: "n"(N) : "memory");
}
__device__ __forceinline__ void ldsm4(uint32_t* r, uint32_t addr) {
    asm volatile("ldmatrix.sync.aligned.m8n8.x4.shared.b16 {%0,%1,%2,%3}, [%4];"
                 : "=r"(r[0]), "=r"(r[1]), "=r"(r[2]), "=r"(r[3]) : "r"(addr));
}
__device__ __forceinline__ void ldsm4t(uint32_t* r, uint32_t addr) {
    asm volatile("ldmatrix.sync.aligned.m8n8.x4.trans.shared.b16 {%0,%1,%2,%3}, [%4];"
                 : "=r"(r[0]), "=r"(r[1]), "=r"(r[2]), "=r"(r[3]) : "r"(addr));
}
__device__ __forceinline__ void mma16816(float* d, const uint32_t* a, uint32_t b0, uint32_t b1) {
    asm volatile("mma.sync.aligned.m16n8k16.row.col.f32.f16.f16.f32 "
                 "{%0,%1,%2,%3}, {%4,%5,%6,%7}, {%8,%9}, {%0,%1,%2,%3};"
                 : "+f"(d[0]), "+f"(d[1]), "+f"(d[2]), "+f"(d[3])
                 : "r"(a[0]), "r"(a[1]), "r"(a[2]), "r"(a[3]), "r"(b0), "r"(b1));
}
__device__ __forceinline__ uint32_t pack_h2(float a, float b) {
    __half2 h = __floats2half2_rn(a, b);
    return *(uint32_t*)&h;
}

// ============================================================
// LayerNorm -> fp16 [row][1024]
// ============================================================
__global__ void __launch_bounds__(256) ln_kernel(
    const float* __restrict__ x, const float* __restrict__ gamma,
    const float* __restrict__ beta, __half* __restrict__ xn)
{
    int row = blockIdx.x;
    int tid = threadIdx.x;
    const float* xr = x + (size_t)row * HD;
    float4 v = *(const float4*)&xr[tid * 4];
    float s  = v.x + v.y + v.z + v.w;
    float ss = v.x * v.x + v.y * v.y + v.z * v.z + v.w * v.w;
    #pragma unroll
    for (int o = 16; o; o >>= 1) {
        s  += __shfl_xor_sync(0xffffffffu, s,  o);
        ss += __shfl_xor_sync(0xffffffffu, ss, o);
    }
    __shared__ float rs[8], rss[8];
    if ((tid & 31) == 0) { rs[tid >> 5] = s; rss[tid >> 5] = ss; }
    __syncthreads();
    s = 0.f; ss = 0.f;
    #pragma unroll
    for (int i = 0; i < 8; i++) { s += rs[i]; ss += rss[i]; }
    float mu  = s * (1.0f / HD);
    float inv = rsqrtf(ss * (1.0f / HD) - mu * mu + 1e-5f);
    float4 g  = *(const float4*)&gamma[tid * 4];
    float4 be = *(const float4*)&beta[tid * 4];
    uint32_t p0 = pack_h2((v.x - mu) * inv * g.x + be.x, (v.y - mu) * inv * g.y + be.y);
    uint32_t p1 = pack_h2((v.z - mu) * inv * g.z + be.z, (v.w - mu) * inv * g.w + be.w);
    ull pk = (ull)p0 | ((ull)p1 << 32);
    *(ull*)&xn[(size_t)row * 1024 + tid * 4] = pk;
}

// all four weights -> fp16 in one launch
__global__ void __launch_bounds__(256) conv_half4(
    const float* __restrict__ W0, const float* __restrict__ W1,
    const float* __restrict__ W2, const float* __restrict__ W3,
    __half* __restrict__ Wh)
{
    int sel = blockIdx.x >> 10;
    const float* src = (sel == 0) ? W0 : (sel == 1) ? W1 : (sel == 2) ? W2 : W3;
    int i = (blockIdx.x & 1023) * 256 + threadIdx.x;
    float4 v = ((const float4*)src)[i];
    ull pk = (ull)pack_h2(v.x, v.y) | ((ull)pack_h2(v.z, v.w) << 32);
    *(ull*)&Wh[((size_t)sel << 20) + (size_t)i * 4] = pk;
}

// ============================================================
// mma.sync fp16 GEMM core (unchanged): CTA 128x128, 8 warps,
// warp 32x64, K-chunk 32, 3-stage cp.async.
// ============================================================
constexpr int GPITCH = 80;
constexpr int MAT_STAGE = 128 * GPITCH;
constexpr int STAGE_BYTES = 2 * MAT_STAGE;
constexpr int GSTG = 3;
constexpr int GEMM_SMEM = GSTG * STAGE_BYTES;
constexpr int NCHUNK = 32;

__device__ __forceinline__ void gemm_load_chunk(
    const __half* __restrict__ A2, const __half* __restrict__ B2,
    int m0, int n0, int c, uint32_t sbase, int tid)
{
    int s = c % GSTG;
    int kc = c * 32;
    uint32_t aSt = sbase + s * STAGE_BYTES;
    uint32_t bSt = aSt + MAT_STAGE;
    #pragma unroll
    for (int p = 0; p < 2; p++) {
        int e = tid + (p << 8);
        int r = e >> 2, cc = e & 3;
        cpasync16(aSt + r * GPITCH + cc * 16, A2 + (size_t)(m0 + r) * 1024 + kc + cc * 8);
        cpasync16(bSt + r * GPITCH + cc * 16, B2 + (size_t)(n0 + r) * 1024 + kc + cc * 8);
    }
    cpcommit();
}

__device__ __forceinline__ void gemm_core(
    const __half* A2, const __half* B2,
    int m0, int n0, uint32_t sbase, int tid, int lane, int wm, int wn,
    float d[2][8][4])
{
    gemm_load_chunk(A2, B2, m0, n0, 0, sbase, tid);
    gemm_load_chunk(A2, B2, m0, n0, 1, sbase, tid);
    int lr = lane & 15;
    int lk = (lane >> 4) << 3;
    for (int c = 0; c < NCHUNK; c++) {
        cpwait<1>();
        __syncthreads();
        if (c + 2 < NCHUNK) gemm_load_chunk(A2, B2, m0, n0, c + 2, sbase, tid);
        else cpcommit();
        uint32_t aSt = sbase + (c % GSTG) * STAGE_BYTES;
        uint32_t bSt = aSt + MAT_STAGE;
        #pragma unroll
        for (int k16 = 0; k16 < 2; k16++) {
            uint32_t a[2][4], b[4][4];
            #pragma unroll
            for (int mt = 0; mt < 2; mt++)
                ldsm4(a[mt], aSt + (wm * 32 + mt * 16 + lr) * GPITCH + (k16 * 16 + lk) * 2);
            #pragma unroll
            for (int nt = 0; nt < 4; nt++)
                ldsm4(b[nt], bSt + (wn * 64 + nt * 16 + lr) * GPITCH + (k16 * 16 + lk) * 2);
            #pragma unroll
            for (int mt = 0; mt < 2; mt++)
                #pragma unroll
                for (int n8 = 0; n8 < 8; n8++) {
                    int nt = n8 >> 1, odd = n8 & 1;
                    mma16816(d[mt][n8], a[mt], b[nt][odd], b[nt][odd + 2]);
                }
        }
        __syncthreads();
    }
}

// Fused QKV: B = concat(Wq,Wk,Wv) 3072x1024; fp16 out [B,NH,T,128]
__global__ void __launch_bounds__(256, 2) gemm_mma_qkv(
    const __half* __restrict__ A2, const __half* __restrict__ Ball,
    __half* __restrict__ Qo, __half* __restrict__ Ko, __half* __restrict__ Vo,
    float qscale)
{
    extern __shared__ char sm[];
    uint32_t sbase = s2u(sm);
    int tid = threadIdx.x, lane = tid & 31, warp = tid >> 5;
    int wm = warp >> 1, wn = warp & 1;
    int m0 = blockIdx.y << 7, n0 = blockIdx.x << 7;
    int sel = n0 >> 10;
    __half* outp = (sel == 0) ? Qo : (sel == 1) ? Ko : Vo;
    float scale = (sel == 0) ? qscale : 1.0f;

    float d[2][8][4];
    #pragma unroll
    for (int i = 0; i < 2; i++)
        #pragma unroll
        for (int j = 0; j < 8; j++)
            #pragma unroll
            for (int q = 0; q < 4; q++) d[i][j][q] = 0.f;

    gemm_core(A2, Ball, m0, n0, sbase, tid, lane, wm, wn, d);

    int mb = m0 + wm * 32 + (lane >> 2);
    int nb = n0 + wn * 64 + (lane & 3) * 2;
    #pragma unroll
    for (int mt = 0; mt < 2; mt++) {
        #pragma unroll
        for (int n8 = 0; n8 < 8; n8++) {
            int n = nb + n8 * 8;
            #pragma unroll
            for (int half = 0; half < 2; half++) {
                int m = mb + mt * 16 + half * 8;
                float c0 = d[mt][n8][half * 2] * scale, c1 = d[mt][n8][half * 2 + 1] * scale;
                int bI = m >> 11, t = m & 2047;
                int h = (n >> 7) & 7, dd = n & 127;
                size_t base = ((size_t)(bI * NH + h) * TT + t) * 128 + dd;
                *(uint32_t*)&outp[base] = pack_h2(c0, c1);
            }
        }
    }
}

// Output-projection: fp32 + residual
__global__ void __launch_bounds__(256, 2) gemm_mma_out(
    const __half* __restrict__ A2, const __half* __restrict__ B2,
    float* __restrict__ C, const float* __restrict__ R)
{
    extern __shared__ char sm[];
    uint32_t sbase = s2u(sm);
    int tid = threadIdx.x, lane = tid & 31, warp = tid >> 5;
    int wm = warp >> 1, wn = warp & 1;
    int m0 = blockIdx.y << 7, n0 = blockIdx.x << 7;

    float d[2][8][4];
    #pragma unroll
    for (int i = 0; i < 2; i++)
        #pragma unroll
        for (int j = 0; j < 8; j++)
            #pragma unroll
            for (int q = 0; q < 4; q++) d[i][j][q] = 0.f;

    gemm_core(A2, B2, m0, n0, sbase, tid, lane, wm, wn, d);

    int mb = m0 + wm * 32 + (lane >> 2);
    int nb = n0 + wn * 64 + (lane & 3) * 2;
    #pragma unroll
    for (int mt = 0; mt < 2; mt++) {
        #pragma unroll
        for (int n8 = 0; n8 < 8; n8++) {
            int n = nb + n8 * 8;
            #pragma unroll
            for (int half = 0; half < 2; half++) {
                int m = mb + mt * 16 + half * 8;
                size_t idx = (size_t)m * HD + n;
                float2 rr = *(const float2*)&R[idx];
                *(float2*)&C[idx] = make_float2(d[mt][n8][half * 2] + rr.x,
                                                d[mt][n8][half * 2 + 1] + rr.y);
            }
        }
    }
}

// ============================================================
// Flash attention FA2: BM=64, BN=64, 4 warps x 16 rows, 128 thr.
// smem = 87KB -> TWO independent CTAs per SM; their softmax /
// MMA phases interleave across CTAs (desynchronized stalls).
// Q fragments register-resident; S-accum reused as A of P@V.
// Q pre-scaled by scale*log2(e); base-2 softmax.
// ============================================================
constexpr int FPB = 272;                      // row pitch bytes
constexpr int FL_Q = 0;                       // 64 x FPB
constexpr int FL_K = FL_Q + 64 * FPB;         // 2 bufs x 64 x FPB
constexpr int FL_V = FL_K + 2 * 64 * FPB;
constexpr int FLASH_SMEM = FL_V + 2 * 64 * FPB;   // 87040 B

__global__ void __launch_bounds__(128, 2) flash_mma(
    const __half* __restrict__ Q2, const __half* __restrict__ K2,
    const __half* __restrict__ V2, __half* __restrict__ Aout)
{
    extern __shared__ char sm[];
    uint32_t sb = s2u(sm);
    int tid = threadIdx.x, lane = tid & 31, w = tid >> 5;   // 4 warps
    int g = lane >> 2, tig = lane & 3;
    int qb = gridDim.x - 1 - blockIdx.x;      // largest tiles first
    int bh = blockIdx.y;
    int q0 = qb << 6;
    const __half* qp = Q2 + (size_t)bh * TT * 128;
    const __half* kp = K2 + (size_t)bh * TT * 128;
    const __half* vp = V2 + (size_t)bh * TT * 128;

    // prologue: Q tile + K/V block 0 (64 rows each), one group
    #pragma unroll
    for (int p = 0; p < 8; p++) {
        int e = tid + (p << 7);
        int r = e >> 4, c = e & 15;
        cpasync16(sb + FL_Q + r * FPB + c * 16, qp + (size_t)(q0 + r) * 128 + c * 8);
        cpasync16(sb + FL_K + r * FPB + c * 16, kp + (size_t)r * 128 + c * 8);
        cpasync16(sb + FL_V + r * FPB + c * 16, vp + (size_t)r * 128 + c * 8);
    }
    cpcommit();
    cpwait<0>();
    __syncthreads();

    int lr = lane & 15;
    int lk = (lane >> 4) << 3;

    // Q -> registers (A fragments for all 8 k16 chunks)
    uint32_t qf[8][4];
    #pragma unroll
    for (int c8 = 0; c8 < 8; c8++)
        ldsm4(qf[c8], sb + FL_Q + (w * 16 + lr) * FPB + (c8 * 16 + lk) * 2);

    float o[16][4];
    #pragma unroll
    for (int i = 0; i < 16; i++)
        #pragma unroll
        for (int j = 0; j < 4; j++) o[i][j] = 0.f;
    float m0r = -1e30f, m1r = -1e30f, l0r = 0.f, l1r = 0.f;

    int nkb = qb + 1;
    for (int kb = 0; kb < nkb; kb++) {
        int buf = kb & 1;
        __syncthreads();   // all warps done reading buf^1 (step kb-2)
        if (kb + 1 < nkb) {
            int kn0 = (kb + 1) << 6;
            uint32_t kD = sb + FL_K + (buf ^ 1) * 64 * FPB;
            uint32_t vD = sb + FL_V + (buf ^ 1) * 64 * FPB;
            #pragma unroll
            for (int p = 0; p < 8; p++) {
                int e = tid + (p << 7);
                int r = e >> 4, c = e & 15;
                cpasync16(kD + r * FPB + c * 16, kp + (size_t)(kn0 + r) * 128 + c * 8);
                cpasync16(vD + r * FPB + c * 16, vp + (size_t)(kn0 + r) * 128 + c * 8);
            }
        }
        cpcommit();
        cpwait<1>();
        __syncthreads();

        uint32_t kB = sb + FL_K + buf * 64 * FPB;
        uint32_t vB = sb + FL_V + buf * 64 * FPB;

        // ---- S = Q K^T : warp computes 16x64 ----
        float s[8][4];
        #pragma unroll
        for (int i = 0; i < 8; i++)
            #pragma unroll
            for (int j = 0; j < 4; j++) s[i][j] = 0.f;
        #pragma unroll
        for (int k16 = 0; k16 < 8; k16++) {
            #pragma unroll
            for (int t = 0; t < 4; t++) {
                uint32_t b[4];
                ldsm4(b, kB + (t * 16 + lr) * FPB + (k16 * 16 + lk) * 2);
                mma16816(s[2 * t],     qf[k16], b[0], b[2]);
                mma16816(s[2 * t + 1], qf[k16], b[1], b[3]);
            }
        }

        // causal mask: only the diagonal block
        if (kb == qb) {
            int rg0 = q0 + w * 16 + g;
            int rg1 = rg0 + 8;
            int cgb = (kb << 6) + tig * 2;
            #pragma unroll
            for (int j = 0; j < 8; j++) {
                int cg = cgb + j * 8;
                if (cg     > rg0) s[j][0] = -1e30f;
                if (cg + 1 > rg0) s[j][1] = -1e30f;
                if (cg     > rg1) s[j][2] = -1e30f;
                if (cg + 1 > rg1) s[j][3] = -1e30f;
            }
        }

        // ---- warp-local softmax (rows g, g+8) ----
        float mx0 = -1e30f, mx1 = -1e30f;
        #pragma unroll
        for (int j = 0; j < 8; j++) {
            mx0 = fmaxf(mx0, fmaxf(s[j][0], s[j][1]));
            mx1 = fmaxf(mx1, fmaxf(s[j][2], s[j][3]));
        }
        mx0 = fmaxf(mx0, __shfl_xor_sync(0xffffffffu, mx0, 1));
        mx0 = fmaxf(mx0, __shfl_xor_sync(0xffffffffu, mx0, 2));
        mx1 = fmaxf(mx1, __shfl_xor_sync(0xffffffffu, mx1, 1));
        mx1 = fmaxf(mx1, __shfl_xor_sync(0xffffffffu, mx1, 2));
        float mn0 = fmaxf(m0r, mx0), mn1 = fmaxf(m1r, mx1);
        float al0 = exp2f(m0r - mn0), al1 = exp2f(m1r - mn1);
        m0r = mn0; m1r = mn1;

        float ps0 = 0.f, ps1 = 0.f;
        #pragma unroll
        for (int j = 0; j < 8; j++) {
            s[j][0] = exp2f(s[j][0] - mn0);
            s[j][1] = exp2f(s[j][1] - mn0);
            s[j][2] = exp2f(s[j][2] - mn1);
            s[j][3] = exp2f(s[j][3] - mn1);
            ps0 += s[j][0] + s[j][1];
            ps1 += s[j][2] + s[j][3];
        }
        ps0 += __shfl_xor_sync(0xffffffffu, ps0, 1);
        ps0 += __shfl_xor_sync(0xffffffffu, ps0, 2);
        ps1 += __shfl_xor_sync(0xffffffffu, ps1, 1);
        ps1 += __shfl_xor_sync(0xffffffffu, ps1, 2);
        l0r = l0r * al0 + ps0;
        l1r = l1r * al1 + ps1;

        // rescale O (skip when max unchanged warp-wide)
        if (!__all_sync(0xffffffffu, (al0 == 1.f) & (al1 == 1.f))) {
            #pragma unroll
            for (int j = 0; j < 16; j++) {
                o[j][0] *= al0; o[j][1] *= al0;
                o[j][2] *= al1; o[j][3] *= al1;
            }
        }

        // P fragments straight from S accumulators
        uint32_t pa[4][4];
        #pragma unroll
        for (int c = 0; c < 4; c++) {
            pa[c][0] = pack_h2(s[2 * c][0],     s[2 * c][1]);
            pa[c][1] = pack_h2(s[2 * c][2],     s[2 * c][3]);
            pa[c][2] = pack_h2(s[2 * c + 1][0], s[2 * c + 1][1]);
            pa[c][3] = pack_h2(s[2 * c + 1][2], s[2 * c + 1][3]);
        }

        // ---- O += P V : warp computes 16x128 ----
        #pragma unroll
        for (int c = 0; c < 4; c++) {
            #pragma unroll
            for (int j = 0; j < 8; j++) {
                uint32_t bt[4];
                ldsm4t(bt, vB + (c * 16 + lr) * FPB + (j * 16 + lk) * 2);
                mma16816(o[2 * j],     pa[c], bt[0], bt[1]);
                mma16816(o[2 * j + 1], pa[c], bt[2], bt[3]);
            }
        }
    }

    // epilogue: normalize, fp16 store [B,T,1024]
    float inv0 = 1.f / l0r, inv1 = 1.f / l1r;
    int b = bh >> 3, h = bh & 7;
    int t0 = q0 + w * 16 + g;
    #pragma unroll
    for (int j = 0; j < 16; j++) {
        int d = j * 8 + tig * 2;
        size_t base0 = (size_t)(b * TT + t0) * 1024 + h * 128 + d;
        size_t base1 = base0 + 8 * 1024;
        *(uint32_t*)&Aout[base0] = pack_h2(o[j][0] * inv0, o[j][1] * inv0);
        *(uint32_t*)&Aout[base1] = pack_h2(o[j][2] * inv1, o[j][3] * inv1);
    }
}

// ============================================================
// Launch
// ============================================================
extern "C" void kernel_launch(void* const* d_in, const int* in_sizes, int n_in,
                              void* d_out, int out_size)
{
    const float* x     = (const float*)d_in[0];
    const float* gamma = (const float*)d_in[1];
    const float* beta  = (const float*)d_in[2];
    const float* Wq    = (const float*)d_in[3];
    const float* Wk    = (const float*)d_in[4];
    const float* Wv    = (const float*)d_in[5];
    const float* Wo    = (const float*)d_in[6];
    float* out = (float*)d_out;

    __half *xn, *w, *q, *k, *v, *attn;
    cudaGetSymbolAddress((void**)&xn,   g_xn);
    cudaGetSymbolAddress((void**)&w,    g_w);
    cudaGetSymbolAddress((void**)&q,    g_q);
    cudaGetSymbolAddress((void**)&k,    g_k);
    cudaGetSymbolAddress((void**)&v,    g_v);
    cudaGetSymbolAddress((void**)&attn, g_attn);

    cudaFuncSetAttribute(gemm_mma_qkv, cudaFuncAttributeMaxDynamicSharedMemorySize, GEMM_SMEM);
    cudaFuncSetAttribute(gemm_mma_out, cudaFuncAttributeMaxDynamicSharedMemorySize, GEMM_SMEM);
    cudaFuncSetAttribute(flash_mma, cudaFuncAttributeMaxDynamicSharedMemorySize, FLASH_SMEM);

    ln_kernel<<<MM, 256>>>(x, gamma, beta, xn);
    conv_half4<<<4096, 256>>>(Wq, Wk, Wv, Wo, w);

    // scale*log2(e) folded into Q so softmax runs in base 2
    const float qscale = 0.08838834764831845f * 1.44269504088896341f;
    gemm_mma_qkv<<<dim3(24, 64), 256, GEMM_SMEM>>>(xn, w, q, k, v, qscale);

    flash_mma<<<dim3(TT / 64, BB * NH), 128, FLASH_SMEM>>>(q, k, v, attn);

    gemm_mma_out<<<dim3(8, 64), 256, GEMM_SMEM>>>(attn, w + ((size_t)3 << 20), out, x);
}

// round 13
// speedup vs baseline: 1.1022x; 1.0834x over previous
#include <cuda_runtime.h>
#include <cuda_fp16.h>
#include <math.h>
#include <cstdint>

constexpr int HD = 1024;
constexpr int NH = 8;
constexpr int DH = 128;
constexpr int BB = 4;
constexpr int TT = 2048;
constexpr int MM = BB * TT; // 8192

typedef unsigned long long ull;

// ---- scratch (allocation-free) ----
__device__ __half g_xn[MM * 1024];          // LN out fp16
__device__ __half g_w[4][1024 * 1024];      // weights fp16 (contiguous: q,k,v,o)
__device__ __half g_q[32 * TT * 128];       // [B*NH][T][128], pre-scaled
__device__ __half g_k[32 * TT * 128];
__device__ __half g_v[32 * TT * 128];
__device__ __half g_attn[MM * 1024];        // attn fp16 [B,T,1024]

// ============================================================
// helpers
// ============================================================
__device__ __forceinline__ uint32_t s2u(const void* p) {
    uint32_t a;
    asm("{ .reg .u64 t; cvta.to.shared.u64 t, %1; cvt.u32.u64 %0, t; }" : "=r"(a) : "l"(p));
    return a;
}
__device__ __forceinline__ void cpasync16(uint32_t smem, const void* g) {
    asm volatile("cp.async.cg.shared.global [%0], [%1], 16;" :: "r"(smem), "l"(g));
}
__device__ __forceinline__ void cpcommit() { asm volatile("cp.async.commit_group;" ::: "memory"); }
template<int N> __device__ __forceinline__ void cpwait() {
    asm volatile("cp.async.wait_group %0;" :: "n"(N) : "memory");
}
__device__ __forceinline__ void ldsm4(uint32_t* r, uint32_t addr) {
    asm volatile("ldmatrix.sync.aligned.m8n8.x4.shared.b16 {%0,%1,%2,%3}, [%4];"
                 : "=r"(r[0]), "=r"(r[1]), "=r"(r[2]), "=r"(r[3]) : "r"(addr));
}
__device__ __forceinline__ void ldsm4t(uint32_t* r, uint32_t addr) {
    asm volatile("ldmatrix.sync.aligned.m8n8.x4.trans.shared.b16 {%0,%1,%2,%3}, [%4];"
                 : "=r"(r[0]), "=r"(r[1]), "=r"(r[2]), "=r"(r[3]) : "r"(addr));
}
__device__ __forceinline__ void mma16816(float* d, const uint32_t* a, uint32_t b0, uint32_t b1) {
    asm volatile("mma.sync.aligned.m16n8k16.row.col.f32.f16.f16.f32 "
                 "{%0,%1,%2,%3}, {%4,%5,%6,%7}, {%8,%9}, {%0,%1,%2,%3};"
                 : "+f"(d[0]), "+f"(d[1]), "+f"(d[2]), "+f"(d[3])
                 : "r"(a[0]), "r"(a[1]), "r"(a[2]), "r"(a[3]), "r"(b0), "r"(b1));
}
__device__ __forceinline__ uint32_t pack_h2(float a, float b) {
    __half2 h = __floats2half2_rn(a, b);
    return *(uint32_t*)&h;
}

// ============================================================
// LayerNorm -> fp16 [row][1024]
// ============================================================
__global__ void __launch_bounds__(256) ln_kernel(
    const float* __restrict__ x, const float* __restrict__ gamma,
    const float* __restrict__ beta, __half* __restrict__ xn)
{
    int row = blockIdx.x;
    int tid = threadIdx.x;
    const float* xr = x + (size_t)row * HD;
    float4 v = *(const float4*)&xr[tid * 4];
    float s  = v.x + v.y + v.z + v.w;
    float ss = v.x * v.x + v.y * v.y + v.z * v.z + v.w * v.w;
    #pragma unroll
    for (int o = 16; o; o >>= 1) {
        s  += __shfl_xor_sync(0xffffffffu, s,  o);
        ss += __shfl_xor_sync(0xffffffffu, ss, o);
    }
    __shared__ float rs[8], rss[8];
    if ((tid & 31) == 0) { rs[tid >> 5] = s; rss[tid >> 5] = ss; }
    __syncthreads();
    s = 0.f; ss = 0.f;
    #pragma unroll
    for (int i = 0; i < 8; i++) { s += rs[i]; ss += rss[i]; }
    float mu  = s * (1.0f / HD);
    float inv = rsqrtf(ss * (1.0f / HD) - mu * mu + 1e-5f);
    float4 g  = *(const float4*)&gamma[tid * 4];
    float4 be = *(const float4*)&beta[tid * 4];
    uint32_t p0 = pack_h2((v.x - mu) * inv * g.x + be.x, (v.y - mu) * inv * g.y + be.y);
    uint32_t p1 = pack_h2((v.z - mu) * inv * g.z + be.z, (v.w - mu) * inv * g.w + be.w);
    ull pk = (ull)p0 | ((ull)p1 << 32);
    *(ull*)&xn[(size_t)row * 1024 + tid * 4] = pk;
}

// all four weights -> fp16 in one launch
__global__ void __launch_bounds__(256) conv_half4(
    const float* __restrict__ W0, const float* __restrict__ W1,
    const float* __restrict__ W2, const float* __restrict__ W3,
    __half* __restrict__ Wh)
{
    int sel = blockIdx.x >> 10;
    const float* src = (sel == 0) ? W0 : (sel == 1) ? W1 : (sel == 2) ? W2 : W3;
    int i = (blockIdx.x & 1023) * 256 + threadIdx.x;
    float4 v = ((const float4*)src)[i];
    ull pk = (ull)pack_h2(v.x, v.y) | ((ull)pack_h2(v.z, v.w) << 32);
    *(ull*)&Wh[((size_t)sel << 20) + (size_t)i * 4] = pk;
}

// ============================================================
// mma.sync fp16 GEMM: CTA 128x128, 8 warps (4m x 2n), warp 32x64,
// K-chunk 32, 4-stage cp.async, fragment double-buffer pipeline.
// Hazard rules: consume stage data only after cpwait + BARRIER
// (cp.async completion is per-thread); write stage c%4 only after
// the barrier that retires all reads of stage c.
// ============================================================
constexpr int GPITCH = 80;
constexpr int MAT_STAGE = 128 * GPITCH;
constexpr int STAGE_BYTES = 2 * MAT_STAGE;   // 20480
constexpr int GSTG = 4;
constexpr int GEMM_SMEM = GSTG * STAGE_BYTES; // 81920
constexpr int NCHUNK = 32;

__device__ __forceinline__ void gemm_load_chunk(
    const __half* __restrict__ A2, const __half* __restrict__ B2,
    int m0, int n0, int c, uint32_t sbase, int tid)
{
    int s = c % GSTG;
    int kc = c * 32;
    uint32_t aSt = sbase + s * STAGE_BYTES;
    uint32_t bSt = aSt + MAT_STAGE;
    #pragma unroll
    for (int p = 0; p < 2; p++) {
        int e = tid + (p << 8);
        int r = e >> 2, cc = e & 3;
        cpasync16(aSt + r * GPITCH + cc * 16, A2 + (size_t)(m0 + r) * 1024 + kc + cc * 8);
        cpasync16(bSt + r * GPITCH + cc * 16, B2 + (size_t)(n0 + r) * 1024 + kc + cc * 8);
    }
    cpcommit();
}

__device__ __forceinline__ void load_frags(
    uint32_t a[2][4], uint32_t b[4][4], uint32_t aSt, uint32_t bSt,
    int k16, int wm, int wn, int lr, int lk)
{
    #pragma unroll
    for (int mt = 0; mt < 2; mt++)
        ldsm4(a[mt], aSt + (wm * 32 + mt * 16 + lr) * GPITCH + (k16 * 16 + lk) * 2);
    #pragma unroll
    for (int nt = 0; nt < 4; nt++)
        ldsm4(b[nt], bSt + (wn * 64 + nt * 16 + lr) * GPITCH + (k16 * 16 + lk) * 2);
}

__device__ __forceinline__ void mma_set(float d[2][8][4], uint32_t a[2][4], uint32_t b[4][4])
{
    #pragma unroll
    for (int mt = 0; mt < 2; mt++)
        #pragma unroll
        for (int n8 = 0; n8 < 8; n8++) {
            int nt = n8 >> 1, odd = n8 & 1;
            mma16816(d[mt][n8], a[mt], b[nt][odd], b[nt][odd + 2]);
        }
}

__device__ __forceinline__ void gemm_core(
    const __half* A2, const __half* B2,
    int m0, int n0, uint32_t sbase, int tid, int lane, int wm, int wn,
    float d[2][8][4])
{
    int lr = lane & 15;
    int lk = (lane >> 4) << 3;

    // prologue: 4 stages in flight
    gemm_load_chunk(A2, B2, m0, n0, 0, sbase, tid);
    gemm_load_chunk(A2, B2, m0, n0, 1, sbase, tid);
    gemm_load_chunk(A2, B2, m0, n0, 2, sbase, tid);
    gemm_load_chunk(A2, B2, m0, n0, 3, sbase, tid);
    cpwait<2>();          // own chunks 0,1 done
    __syncthreads();      // -> chunks 0,1 globally visible

    uint32_t fa[2][2][4], fb[2][4][4];
    load_frags(fa[0], fb[0], sbase, sbase + MAT_STAGE, 0, wm, wn, lr, lk);

    for (int c = 0; c < NCHUNK; c++) {
        // invariant at top: chunks <= c+1 globally visible; frags for
        // (chunk c, k16=0) already in fa[0]/fb[0].
        uint32_t aSt  = sbase + (c % GSTG) * STAGE_BYTES;
        uint32_t bSt  = aSt + MAT_STAGE;
        uint32_t aStN = sbase + ((c + 1) % GSTG) * STAGE_BYTES;
        uint32_t bStN = aStN + MAT_STAGE;

        load_frags(fa[1], fb[1], aSt, bSt, 1, wm, wn, lr, lk);   // k16=1 of chunk c
        mma_set(d, fa[0], fb[0]);
        if (c + 1 < NCHUNK)
            load_frags(fa[0], fb[0], aStN, bStN, 0, wm, wn, lr, lk); // k16=0 of chunk c+1
        mma_set(d, fa[1], fb[1]);

        __syncthreads();   // retire all reads of stage c (and prefetch reads)
        if (c + 4 < NCHUNK) gemm_load_chunk(A2, B2, m0, n0, c + 4, sbase, tid);
        else cpcommit();
        cpwait<2>();       // own chunks <= c+2 done
        __syncthreads();   // -> chunks <= c+2 globally visible
    }
}

// Fused QKV: B = concat(Wq,Wk,Wv) 3072x1024; fp16 out [B,NH,T,128]
__global__ void __launch_bounds__(256, 2) gemm_mma_qkv(
    const __half* __restrict__ A2, const __half* __restrict__ Ball,
    __half* __restrict__ Qo, __half* __restrict__ Ko, __half* __restrict__ Vo,
    float qscale)
{
    extern __shared__ char sm[];
    uint32_t sbase = s2u(sm);
    int tid = threadIdx.x, lane = tid & 31, warp = tid >> 5;
    int wm = warp >> 1, wn = warp & 1;
    int m0 = blockIdx.y << 7, n0 = blockIdx.x << 7;
    int sel = n0 >> 10;
    __half* outp = (sel == 0) ? Qo : (sel == 1) ? Ko : Vo;
    float scale = (sel == 0) ? qscale : 1.0f;

    float d[2][8][4];
    #pragma unroll
    for (int i = 0; i < 2; i++)
        #pragma unroll
        for (int j = 0; j < 8; j++)
            #pragma unroll
            for (int q = 0; q < 4; q++) d[i][j][q] = 0.f;

    gemm_core(A2, Ball, m0, n0, sbase, tid, lane, wm, wn, d);

    int mb = m0 + wm * 32 + (lane >> 2);
    int nb = n0 + wn * 64 + (lane & 3) * 2;
    #pragma unroll
    for (int mt = 0; mt < 2; mt++) {
        #pragma unroll
        for (int n8 = 0; n8 < 8; n8++) {
            int n = nb + n8 * 8;
            #pragma unroll
            for (int half = 0; half < 2; half++) {
                int m = mb + mt * 16 + half * 8;
                float c0 = d[mt][n8][half * 2] * scale, c1 = d[mt][n8][half * 2 + 1] * scale;
                int bI = m >> 11, t = m & 2047;
                int h = (n >> 7) & 7, dd = n & 127;
                size_t base = ((size_t)(bI * NH + h) * TT + t) * 128 + dd;
                *(uint32_t*)&outp[base] = pack_h2(c0, c1);
            }
        }
    }
}

// Output-projection: fp32 + residual
__global__ void __launch_bounds__(256, 2) gemm_mma_out(
    const __half* __restrict__ A2, const __half* __restrict__ B2,
    float* __restrict__ C, const float* __restrict__ R)
{
    extern __shared__ char sm[];
    uint32_t sbase = s2u(sm);
    int tid = threadIdx.x, lane = tid & 31, warp = tid >> 5;
    int wm = warp >> 1, wn = warp & 1;
    int m0 = blockIdx.y << 7, n0 = blockIdx.x << 7;

    float d[2][8][4];
    #pragma unroll
    for (int i = 0; i < 2; i++)
        #pragma unroll
        for (int j = 0; j < 8; j++)
            #pragma unroll
            for (int q = 0; q < 4; q++) d[i][j][q] = 0.f;

    gemm_core(A2, B2, m0, n0, sbase, tid, lane, wm, wn, d);

    int mb = m0 + wm * 32 + (lane >> 2);
    int nb = n0 + wn * 64 + (lane & 3) * 2;
    #pragma unroll
    for (int mt = 0; mt < 2; mt++) {
        #pragma unroll
        for (int n8 = 0; n8 < 8; n8++) {
            int n = nb + n8 * 8;
            #pragma unroll
            for (int half = 0; half < 2; half++) {
                int m = mb + mt * 16 + half * 8;
                size_t idx = (size_t)m * HD + n;
                float2 rr = *(const float2*)&R[idx];
                *(float2*)&C[idx] = make_float2(d[mt][n8][half * 2] + rr.x,
                                                d[mt][n8][half * 2 + 1] + rr.y);
            }
        }
    }
}

// ============================================================
// Flash attention FA2: BM=64, BN=64, 4 warps x 16 rows, 128 thr,
// 2 CTAs/SM. S/PV phases use 3-slot ldmatrix register rotation.
// Sync structure identical to the R11 kernel (wait -> barrier ->
// read), which is race-free.
// ============================================================
constexpr int FPB = 272;                      // row pitch bytes
constexpr int FL_Q = 0;                       // 64 x FPB
constexpr int FL_K = FL_Q + 64 * FPB;         // 2 bufs x 64 x FPB
constexpr int FL_V = FL_K + 2 * 64 * FPB;
constexpr int FLASH_SMEM = FL_V + 2 * 64 * FPB;   // 87040 B

__global__ void __launch_bounds__(128, 2) flash_mma(
    const __half* __restrict__ Q2, const __half* __restrict__ K2,
    const __half* __restrict__ V2, __half* __restrict__ Aout)
{
    extern __shared__ char sm[];
    uint32_t sb = s2u(sm);
    int tid = threadIdx.x, lane = tid & 31, w = tid >> 5;   // 4 warps
    int g = lane >> 2, tig = lane & 3;
    int qb = gridDim.x - 1 - blockIdx.x;      // largest tiles first
    int bh = blockIdx.y;
    int q0 = qb << 6;
    const __half* qp = Q2 + (size_t)bh * TT * 128;
    const __half* kp = K2 + (size_t)bh * TT * 128;
    const __half* vp = V2 + (size_t)bh * TT * 128;

    // prologue: Q tile + K/V block 0 (64 rows each), one group
    #pragma unroll
    for (int p = 0; p < 8; p++) {
        int e = tid + (p << 7);
        int r = e >> 4, c = e & 15;
        cpasync16(sb + FL_Q + r * FPB + c * 16, qp + (size_t)(q0 + r) * 128 + c * 8);
        cpasync16(sb + FL_K + r * FPB + c * 16, kp + (size_t)r * 128 + c * 8);
        cpasync16(sb + FL_V + r * FPB + c * 16, vp + (size_t)r * 128 + c * 8);
    }
    cpcommit();
    cpwait<0>();
    __syncthreads();

    int lr = lane & 15;
    int lk = (lane >> 4) << 3;

    // Q -> registers (A fragments for all 8 k16 chunks)
    uint32_t qf[8][4];
    #pragma unroll
    for (int c8 = 0; c8 < 8; c8++)
        ldsm4(qf[c8], sb + FL_Q + (w * 16 + lr) * FPB + (c8 * 16 + lk) * 2);

    float o[16][4];
    #pragma unroll
    for (int i = 0; i < 16; i++)
        #pragma unroll
        for (int j = 0; j < 4; j++) o[i][j] = 0.f;
    float m0r = -1e30f, m1r = -1e30f, l0r = 0.f, l1r = 0.f;

    int nkb = qb + 1;
    for (int kb = 0; kb < nkb; kb++) {
        int buf = kb & 1;
        __syncthreads();   // all warps done reading buf^1 (step kb-2)
        if (kb + 1 < nkb) {
            int kn0 = (kb + 1) << 6;
            uint32_t kD = sb + FL_K + (buf ^ 1) * 64 * FPB;
            uint32_t vD = sb + FL_V + (buf ^ 1) * 64 * FPB;
            #pragma unroll
            for (int p = 0; p < 8; p++) {
                int e = tid + (p << 7);
                int r = e >> 4, c = e & 15;
                cpasync16(kD + r * FPB + c * 16, kp + (size_t)(kn0 + r) * 128 + c * 8);
                cpasync16(vD + r * FPB + c * 16, vp + (size_t)(kn0 + r) * 128 + c * 8);
            }
        }
        cpcommit();
        cpwait<1>();
        __syncthreads();

        uint32_t kB = sb + FL_K + buf * 64 * FPB;
        uint32_t vB = sb + FL_V + buf * 64 * FPB;

        // ---- S = Q K^T : warp computes 16x64, pipelined ldsm ----
        float s[8][4];
        #pragma unroll
        for (int i = 0; i < 8; i++)
            #pragma unroll
            for (int j = 0; j < 4; j++) s[i][j] = 0.f;
        {
            uint32_t rb[3][4];
            ldsm4(rb[0], kB + (0 * 16 + lr) * FPB + (0 * 16 + lk) * 2);   // i=0: t0,k0
            ldsm4(rb[1], kB + (1 * 16 + lr) * FPB + (0 * 16 + lk) * 2);   // i=1: t1,k0
            #pragma unroll
            for (int i = 0; i < 32; i++) {
                if (i + 2 < 32) {
                    int k2 = (i + 2) >> 2, t2 = (i + 2) & 3;
                    ldsm4(rb[(i + 2) % 3], kB + (t2 * 16 + lr) * FPB + (k2 * 16 + lk) * 2);
                }
                int k16 = i >> 2, t = i & 3;
                uint32_t* b = rb[i % 3];
                mma16816(s[2 * t],     qf[k16], b[0], b[2]);
                mma16816(s[2 * t + 1], qf[k16], b[1], b[3]);
            }
        }

        // causal mask: only the diagonal block
        if (kb == qb) {
            int rg0 = q0 + w * 16 + g;
            int rg1 = rg0 + 8;
            int cgb = (kb << 6) + tig * 2;
            #pragma unroll
            for (int j = 0; j < 8; j++) {
                int cg = cgb + j * 8;
                if (cg     > rg0) s[j][0] = -1e30f;
                if (cg + 1 > rg0) s[j][1] = -1e30f;
                if (cg     > rg1) s[j][2] = -1e30f;
                if (cg + 1 > rg1) s[j][3] = -1e30f;
            }
        }

        // ---- warp-local softmax (rows g, g+8) ----
        float mx0 = -1e30f, mx1 = -1e30f;
        #pragma unroll
        for (int j = 0; j < 8; j++) {
            mx0 = fmaxf(mx0, fmaxf(s[j][0], s[j][1]));
            mx1 = fmaxf(mx1, fmaxf(s[j][2], s[j][3]));
        }
        mx0 = fmaxf(mx0, __shfl_xor_sync(0xffffffffu, mx0, 1));
        mx0 = fmaxf(mx0, __shfl_xor_sync(0xffffffffu, mx0, 2));
        mx1 = fmaxf(mx1, __shfl_xor_sync(0xffffffffu, mx1, 1));
        mx1 = fmaxf(mx1, __shfl_xor_sync(0xffffffffu, mx1, 2));
        float mn0 = fmaxf(m0r, mx0), mn1 = fmaxf(m1r, mx1);
        float al0 = exp2f(m0r - mn0), al1 = exp2f(m1r - mn1);
        m0r = mn0; m1r = mn1;

        float ps0 = 0.f, ps1 = 0.f;
        #pragma unroll
        for (int j = 0; j < 8; j++) {
            s[j][0] = exp2f(s[j][0] - mn0);
            s[j][1] = exp2f(s[j][1] - mn0);
            s[j][2] = exp2f(s[j][2] - mn1);
            s[j][3] = exp2f(s[j][3] - mn1);
            ps0 += s[j][0] + s[j][1];
            ps1 += s[j][2] + s[j][3];
        }
        ps0 += __shfl_xor_sync(0xffffffffu, ps0, 1);
        ps0 += __shfl_xor_sync(0xffffffffu, ps0, 2);
        ps1 += __shfl_xor_sync(0xffffffffu, ps1, 1);
        ps1 += __shfl_xor_sync(0xffffffffu, ps1, 2);
        l0r = l0r * al0 + ps0;
        l1r = l1r * al1 + ps1;

        // rescale O (skip when max unchanged warp-wide)
        if (!__all_sync(0xffffffffu, (al0 == 1.f) & (al1 == 1.f))) {
            #pragma unroll
            for (int j = 0; j < 16; j++) {
                o[j][0] *= al0; o[j][1] *= al0;
                o[j][2] *= al1; o[j][3] *= al1;
            }
        }

        // P fragments straight from S accumulators
        uint32_t pa[4][4];
        #pragma unroll
        for (int c = 0; c < 4; c++) {
            pa[c][0] = pack_h2(s[2 * c][0],     s[2 * c][1]);
            pa[c][1] = pack_h2(s[2 * c][2],     s[2 * c][3]);
            pa[c][2] = pack_h2(s[2 * c + 1][0], s[2 * c + 1][1]);
            pa[c][3] = pack_h2(s[2 * c + 1][2], s[2 * c + 1][3]);
        }

        // ---- O += P V : warp computes 16x128, pipelined ldsm ----
        {
            uint32_t rv[3][4];
            ldsm4t(rv[0], vB + (0 * 16 + lr) * FPB + (0 * 16 + lk) * 2);   // i=0: c0,j0
            ldsm4t(rv[1], vB + (0 * 16 + lr) * FPB + (1 * 16 + lk) * 2);   // i=1: c0,j1
            #pragma unroll
            for (int i = 0; i < 32; i++) {
                if (i + 2 < 32) {
                    int c2 = (i + 2) >> 3, j2 = (i + 2) & 7;
                    ldsm4t(rv[(i + 2) % 3], vB + (c2 * 16 + lr) * FPB + (j2 * 16 + lk) * 2);
                }
                int c = i >> 3, j = i & 7;
                uint32_t* bt = rv[i % 3];
                mma16816(o[2 * j],     pa[c], bt[0], bt[1]);
                mma16816(o[2 * j + 1], pa[c], bt[2], bt[3]);
            }
        }
    }

    // epilogue: normalize, fp16 store [B,T,1024]
    float inv0 = 1.f / l0r, inv1 = 1.f / l1r;
    int b = bh >> 3, h = bh & 7;
    int t0 = q0 + w * 16 + g;
    #pragma unroll
    for (int j = 0; j < 16; j++) {
        int d = j * 8 + tig * 2;
        size_t base0 = (size_t)(b * TT + t0) * 1024 + h * 128 + d;
        size_t base1 = base0 + 8 * 1024;
        *(uint32_t*)&Aout[base0] = pack_h2(o[j][0] * inv0, o[j][1] * inv0);
        *(uint32_t*)&Aout[base1] = pack_h2(o[j][2] * inv1, o[j][3] * inv1);
    }
}

// ============================================================
// Launch
// ============================================================
extern "C" void kernel_launch(void* const* d_in, const int* in_sizes, int n_in,
                              void* d_out, int out_size)
{
    const float* x     = (const float*)d_in[0];
    const float* gamma = (const float*)d_in[1];
    const float* beta  = (const float*)d_in[2];
    const float* Wq    = (const float*)d_in[3];
    const float* Wk    = (const float*)d_in[4];
    const float* Wv    = (const float*)d_in[5];
    const float* Wo    = (const float*)d_in[6];
    float* out = (float*)d_out;

    __half *xn, *w, *q, *k, *v, *attn;
    cudaGetSymbolAddress((void**)&xn,   g_xn);
    cudaGetSymbolAddress((void**)&w,    g_w);
    cudaGetSymbolAddress((void**)&q,    g_q);
    cudaGetSymbolAddress((void**)&k,    g_k);
    cudaGetSymbolAddress((void**)&v,    g_v);
    cudaGetSymbolAddress((void**)&attn, g_attn);

    cudaFuncSetAttribute(gemm_mma_qkv, cudaFuncAttributeMaxDynamicSharedMemorySize, GEMM_SMEM);
    cudaFuncSetAttribute(gemm_mma_out, cudaFuncAttributeMaxDynamicSharedMemorySize, GEMM_SMEM);
    cudaFuncSetAttribute(flash_mma, cudaFuncAttributeMaxDynamicSharedMemorySize, FLASH_SMEM);

    ln_kernel<<<MM, 256>>>(x, gamma, beta, xn);
    conv_half4<<<4096, 256>>>(Wq, Wk, Wv, Wo, w);

    // scale*log2(e) folded into Q so softmax runs in base 2
    const float qscale = 0.08838834764831845f * 1.44269504088896341f;
    gemm_mma_qkv<<<dim3(24, 64), 256, GEMM_SMEM>>>(xn, w, q, k, v, qscale);

    flash_mma<<<dim3(TT / 64, BB * NH), 128, FLASH_SMEM>>>(q, k, v, attn);

    gemm_mma_out<<<dim3(8, 64), 256, GEMM_SMEM>>>(attn, w + ((size_t)3 << 20), out, x);
}